// round 10
// baseline (speedup 1.0000x reference)
#include <cuda_runtime.h>
#include <cuda_bf16.h>
#include <math.h>
#include <cstdint>

#define SEQ_LEN 16384
#define ENC_H   2048
#define DEC_H   2048

#define R       8                       // rows per kA/k1 block
#define NBLK    (SEQ_LEN / R)           // 2048 kA blocks
#define TILE_BYTES (R * ENC_H * 4)      // 64 KB contiguous per block

// Scratch (device globals — no allocation allowed)
__device__ float g_v[ENC_H];
__device__ float g_ctx[NBLK * ENC_H];    // 16 MB per-block partial contexts
__device__ float g_m[NBLK];
__device__ float g_z[NBLK];

__device__ __forceinline__ uint32_t smem_u32(const void* p) {
    uint32_t a;
    asm("{ .reg .u64 tmp; cvta.to.shared.u64 tmp, %1; cvt.u32.u64 %0, tmp; }"
        : "=r"(a) : "l"(p));
    return a;
}

// ---------------------------------------------------------------------------
// Kernel 1: v = W @ dec  (kA skeleton: 256 blocks x 256 thr, bulk 16 LDG)
// ---------------------------------------------------------------------------
__global__ __launch_bounds__(256, 2) void k1_gemv(const float* __restrict__ W,
                                                  const float* __restrict__ dec) {
    __shared__ float s_red[8][R];
    int t    = threadIdx.x;
    int warp = t >> 5;
    int lane = t & 31;
    size_t s0 = (size_t)blockIdx.x * R;

    const float4* d4 = reinterpret_cast<const float4*>(dec);
    float4 v0 = __ldg(&d4[t]);
    float4 v1 = __ldg(&d4[t + 256]);

    float4 r0[R], r1[R];
    #pragma unroll
    for (int r = 0; r < R; ++r) {
        const float4* row = reinterpret_cast<const float4*>(W + (s0 + r) * DEC_H);
        r0[r] = row[t];
        r1[r] = row[t + 256];
    }

    #pragma unroll
    for (int r = 0; r < R; ++r) {
        float d = r0[r].x * v0.x + r0[r].y * v0.y + r0[r].z * v0.z + r0[r].w * v0.w
                + r1[r].x * v1.x + r1[r].y * v1.y + r1[r].z * v1.z + r1[r].w * v1.w;
        #pragma unroll
        for (int o = 16; o > 0; o >>= 1) d += __shfl_xor_sync(0xffffffffu, d, o);
        if (lane == 0) s_red[warp][r] = d;
    }
    __syncthreads();
    if (t < R) {
        float x = 0.0f;
        #pragma unroll
        for (int w = 0; w < 8; ++w) x += s_red[w][t];
        g_v[s0 + t] = x;
    }
}

// ---------------------------------------------------------------------------
// Kernel A: TMA-bulk version. One 64 KB cp.async.bulk per block stages the
// block's 8 contiguous rows into smem; compute (dots, weights, accumulate)
// runs from smem. 3 blocks/SM co-resident -> TMA streams overlap compute.
// ---------------------------------------------------------------------------
__global__ __launch_bounds__(256) void kA_fused(const float* __restrict__ enc) {
    extern __shared__ float s_data[];        // 64 KB: 8 rows x 2048 floats
    __shared__ uint64_t s_mbar;
    __shared__ float s_red[8][R];
    int t    = threadIdx.x;
    int warp = t >> 5;
    int lane = t & 31;
    size_t s0 = (size_t)blockIdx.x * R;

    uint32_t mbar = smem_u32(&s_mbar);
    uint32_t dst  = smem_u32(s_data);

    if (t == 0) {
        asm volatile("mbarrier.init.shared.b64 [%0], 1;" :: "r"(mbar) : "memory");
        asm volatile("fence.proxy.async.shared::cta;" ::: "memory");
    }
    __syncthreads();
    if (t == 0) {
        asm volatile("mbarrier.arrive.expect_tx.shared.b64 _, [%0], %1;"
                     :: "r"(mbar), "r"((uint32_t)TILE_BYTES) : "memory");
        asm volatile(
            "cp.async.bulk.shared::cta.global.mbarrier::complete_tx::bytes "
            "[%0], [%1], %2, [%3];"
            :: "r"(dst), "l"(enc + s0 * ENC_H), "r"((uint32_t)TILE_BYTES), "r"(mbar)
            : "memory");
    }

    // overlap: load v while TMA streams
    const float4* v4 = reinterpret_cast<const float4*>(g_v);
    float4 v0 = __ldg(&v4[t]);
    float4 v1 = __ldg(&v4[t + 256]);

    // wait for the bulk copy (phase 0)
    {
        uint32_t done = 0;
        while (!done) {
            asm volatile(
                "{\n\t.reg .pred p;\n\t"
                "mbarrier.try_wait.parity.acquire.cta.shared::cta.b64 p, [%1], %2;\n\t"
                "selp.b32 %0, 1, 0, p;\n\t}"
                : "=r"(done) : "r"(mbar), "r"(0u) : "memory");
        }
    }

    const float4* s4 = reinterpret_cast<const float4*>(s_data);

    // dots from smem
    float d[R];
    #pragma unroll
    for (int r = 0; r < R; ++r) {
        float4 x0 = s4[r * (ENC_H / 4) + t];
        float4 x1 = s4[r * (ENC_H / 4) + t + 256];
        d[r] = x0.x * v0.x + x0.y * v0.y + x0.z * v0.z + x0.w * v0.w
             + x1.x * v1.x + x1.y * v1.y + x1.z * v1.z + x1.w * v1.w;
    }
    #pragma unroll
    for (int r = 0; r < R; ++r) {
        float x = d[r];
        #pragma unroll
        for (int o = 16; o > 0; o >>= 1) x += __shfl_xor_sync(0xffffffffu, x, o);
        if (lane == 0) s_red[warp][r] = x;
    }
    __syncthreads();

    float sc[R];
    #pragma unroll
    for (int r = 0; r < R; ++r) {
        float x = 0.0f;
        #pragma unroll
        for (int w = 0; w < 8; ++w) x += s_red[w][r];
        sc[r] = x;
    }
    float m = sc[0];
    #pragma unroll
    for (int r = 1; r < R; ++r) m = fmaxf(m, sc[r]);
    float z = 0.0f;
    float w[R];
    #pragma unroll
    for (int r = 0; r < R; ++r) { w[r] = __expf(sc[r] - m); z += w[r]; }

    // weighted accumulate from smem
    float4 a0 = make_float4(0.f, 0.f, 0.f, 0.f);
    float4 a1 = make_float4(0.f, 0.f, 0.f, 0.f);
    #pragma unroll
    for (int r = 0; r < R; ++r) {
        float4 x0 = s4[r * (ENC_H / 4) + t];
        float4 x1 = s4[r * (ENC_H / 4) + t + 256];
        a0.x += w[r] * x0.x; a0.y += w[r] * x0.y;
        a0.z += w[r] * x0.z; a0.w += w[r] * x0.w;
        a1.x += w[r] * x1.x; a1.y += w[r] * x1.y;
        a1.z += w[r] * x1.z; a1.w += w[r] * x1.w;
    }

    float4* ctx = reinterpret_cast<float4*>(g_ctx + (size_t)blockIdx.x * ENC_H);
    ctx[t] = a0;
    ctx[t + 256] = a1;
    if (t == 0) { g_m[blockIdx.x] = m; g_z[blockIdx.x] = z; }
}

// ---------------------------------------------------------------------------
// Kernel B: single-kernel combine over NBLK=2048 partials (R9 shape).
// ---------------------------------------------------------------------------
__global__ __launch_bounds__(256) void kB_combine(float* __restrict__ out) {
    __shared__ float s_e[NBLK];          // 8 KB
    __shared__ float s_red[8];
    __shared__ float s_M, s_invZ;
    __shared__ float4 s_out[8];
    int t    = threadIdx.x;
    int warp = t >> 5;
    int lane = t & 31;

    float m = -INFINITY;
    #pragma unroll
    for (int i = 0; i < NBLK / 256; ++i) m = fmaxf(m, g_m[t + 256 * i]);
    #pragma unroll
    for (int o = 16; o > 0; o >>= 1) m = fmaxf(m, __shfl_xor_sync(0xffffffffu, m, o));
    if (lane == 0) s_red[warp] = m;
    __syncthreads();
    if (t == 0) {
        float mm = s_red[0];
        #pragma unroll
        for (int wdx = 1; wdx < 8; ++wdx) mm = fmaxf(mm, s_red[wdx]);
        s_M = mm;
    }
    __syncthreads();
    float M = s_M;

    float zs = 0.0f;
    #pragma unroll
    for (int i = 0; i < NBLK / 256; ++i) {
        int b = t + 256 * i;
        float e = __expf(g_m[b] - M);
        s_e[b] = e;
        zs += e * g_z[b];
    }
    #pragma unroll
    for (int o = 16; o > 0; o >>= 1) zs += __shfl_xor_sync(0xffffffffu, zs, o);
    __syncthreads();
    if (lane == 0) s_red[warp] = zs;
    __syncthreads();
    if (t == 0) {
        float s = 0.0f;
        #pragma unroll
        for (int wdx = 0; wdx < 8; ++wdx) s += s_red[wdx];
        s_invZ = 1.0f / s;
    }
    __syncthreads();

    int col4 = blockIdx.x * 4 + (warp >> 1);     // [0, 512)
    int half = warp & 1;
    const float4* ctx = reinterpret_cast<const float4*>(g_ctx);
    float4 acc = make_float4(0.f, 0.f, 0.f, 0.f);
    int b0 = half * (NBLK / 2) + lane;
    #pragma unroll 8
    for (int b = b0; b < half * (NBLK / 2) + NBLK / 2; b += 32) {
        float e  = s_e[b];
        float4 c = ctx[(size_t)b * (ENC_H / 4) + col4];
        acc.x += e * c.x; acc.y += e * c.y; acc.z += e * c.z; acc.w += e * c.w;
    }
    #pragma unroll
    for (int o = 16; o > 0; o >>= 1) {
        acc.x += __shfl_xor_sync(0xffffffffu, acc.x, o);
        acc.y += __shfl_xor_sync(0xffffffffu, acc.y, o);
        acc.z += __shfl_xor_sync(0xffffffffu, acc.z, o);
        acc.w += __shfl_xor_sync(0xffffffffu, acc.w, o);
    }
    if (lane == 0) s_out[warp] = acc;
    __syncthreads();
    if (t < 4) {
        float4 a = s_out[2 * t], b = s_out[2 * t + 1];
        float inv = s_invZ;
        float4 r;
        r.x = (a.x + b.x) * inv;
        r.y = (a.y + b.y) * inv;
        r.z = (a.z + b.z) * inv;
        r.w = (a.w + b.w) * inv;
        reinterpret_cast<float4*>(out)[blockIdx.x * 4 + t] = r;
    }
}

extern "C" void kernel_launch(void* const* d_in, const int* in_sizes, int n_in,
                              void* d_out, int out_size) {
    const float* enc = (const float*)d_in[0];   // [16384, 2048]
    const float* dec = (const float*)d_in[1];   // [1, 2048]
    const float* W   = (const float*)d_in[2];   // [2048, 2048]
    float* out = (float*)d_out;                 // [1, 2048]

    static bool attr_set = false;
    if (!attr_set) {
        cudaFuncSetAttribute(kA_fused, cudaFuncAttributeMaxDynamicSharedMemorySize,
                             TILE_BYTES + 256);
        attr_set = true;
    }

    k1_gemv<<<ENC_H / R, 256>>>(W, dec);
    kA_fused<<<NBLK, 256, TILE_BYTES + 256>>>(enc);
    kB_combine<<<128, 256>>>(out);
}

// round 11
// speedup vs baseline: 1.0758x; 1.0758x over previous
#include <cuda_runtime.h>
#include <cuda_bf16.h>
#include <math.h>

#define SEQ_LEN 16384
#define ENC_H   2048
#define DEC_H   2048

#define RA      16                      // rows per kA block
#define NBLK    (SEQ_LEN / RA)          // 1024 kA blocks
#define R1      4                       // rows per k1 block
#define N1BLK   (ENC_H / R1)            // 512 k1 blocks

// Scratch (device globals — no allocation allowed)
__device__ float g_v[ENC_H];
__device__ float g_ctx[NBLK * ENC_H];    // 8 MB per-block partial contexts
__device__ float g_m[NBLK];
__device__ float g_z[NBLK];

// ---------------------------------------------------------------------------
// Kernel 1: v = W @ dec.  512 blocks x 256 thr, 4 rows/block, 8 bulk LDG.128
// per thread -> finer wave granularity (3.46 blocks/SM).
// ---------------------------------------------------------------------------
__global__ __launch_bounds__(256) void k1_gemv(const float* __restrict__ W,
                                               const float* __restrict__ dec) {
    __shared__ float s_red[8][R1];
    int t    = threadIdx.x;
    int warp = t >> 5;
    int lane = t & 31;
    size_t s0 = (size_t)blockIdx.x * R1;

    const float4* d4 = reinterpret_cast<const float4*>(dec);
    float4 v0 = __ldg(&d4[t]);
    float4 v1 = __ldg(&d4[t + 256]);

    float4 r0[R1], r1[R1];
    #pragma unroll
    for (int r = 0; r < R1; ++r) {
        const float4* row = reinterpret_cast<const float4*>(W + (s0 + r) * DEC_H);
        r0[r] = row[t];
        r1[r] = row[t + 256];
    }

    #pragma unroll
    for (int r = 0; r < R1; ++r) {
        float d = r0[r].x * v0.x + r0[r].y * v0.y + r0[r].z * v0.z + r0[r].w * v0.w
                + r1[r].x * v1.x + r1[r].y * v1.y + r1[r].z * v1.z + r1[r].w * v1.w;
        #pragma unroll
        for (int o = 16; o > 0; o >>= 1) d += __shfl_xor_sync(0xffffffffu, d, o);
        if (lane == 0) s_red[warp][r] = d;
    }
    __syncthreads();
    if (t < R1) {
        float x = 0.0f;
        #pragma unroll
        for (int w = 0; w < 8; ++w) x += s_red[w][t];
        g_v[s0 + t] = x;
    }
}

// ---------------------------------------------------------------------------
// Kernel A: single-generation fused pass, 16 rows/block (halves ctx traffic
// vs R=8). 32 independent LDG.128 per thread held in registers; ONE
// reduction round; weights; accumulate. ~160 regs, 8 warps/SM, MLP=32.
// ---------------------------------------------------------------------------
__global__ __launch_bounds__(256, 1) void kA_fused(const float* __restrict__ enc) {
    __shared__ float s_red[8][RA];
    int t    = threadIdx.x;
    int warp = t >> 5;
    int lane = t & 31;
    size_t s0 = (size_t)blockIdx.x * RA;

    const float4* v4 = reinterpret_cast<const float4*>(g_v);
    float4 v0 = v4[t];
    float4 v1 = v4[t + 256];

    float4 r0[RA], r1[RA];
    #pragma unroll
    for (int r = 0; r < RA; ++r) {
        const float4* row = reinterpret_cast<const float4*>(enc + (s0 + r) * ENC_H);
        r0[r] = row[t];
        r1[r] = row[t + 256];
    }

    #pragma unroll
    for (int r = 0; r < RA; ++r) {
        float d = r0[r].x * v0.x + r0[r].y * v0.y + r0[r].z * v0.z + r0[r].w * v0.w
                + r1[r].x * v1.x + r1[r].y * v1.y + r1[r].z * v1.z + r1[r].w * v1.w;
        #pragma unroll
        for (int o = 16; o > 0; o >>= 1) d += __shfl_xor_sync(0xffffffffu, d, o);
        if (lane == 0) s_red[warp][r] = d;
    }
    __syncthreads();

    float sc[RA];
    #pragma unroll
    for (int r = 0; r < RA; ++r) {
        float x = 0.0f;
        #pragma unroll
        for (int w = 0; w < 8; ++w) x += s_red[w][r];
        sc[r] = x;
    }
    float m = sc[0];
    #pragma unroll
    for (int r = 1; r < RA; ++r) m = fmaxf(m, sc[r]);
    float z = 0.0f;
    float w[RA];
    #pragma unroll
    for (int r = 0; r < RA; ++r) { w[r] = __expf(sc[r] - m); z += w[r]; }

    float4 a0 = make_float4(0.f, 0.f, 0.f, 0.f);
    float4 a1 = make_float4(0.f, 0.f, 0.f, 0.f);
    #pragma unroll
    for (int r = 0; r < RA; ++r) {
        a0.x += w[r] * r0[r].x; a0.y += w[r] * r0[r].y;
        a0.z += w[r] * r0[r].z; a0.w += w[r] * r0[r].w;
        a1.x += w[r] * r1[r].x; a1.y += w[r] * r1[r].y;
        a1.z += w[r] * r1[r].z; a1.w += w[r] * r1[r].w;
    }

    float4* ctx = reinterpret_cast<float4*>(g_ctx + (size_t)blockIdx.x * ENC_H);
    ctx[t] = a0;
    ctx[t + 256] = a1;
    if (t == 0) { g_m[blockIdx.x] = m; g_z[blockIdx.x] = z; }
}

// ---------------------------------------------------------------------------
// Kernel B: single-kernel combine over NBLK=1024 partials.
//   grid 128 x 256 thr; 8 warps = 4 col4s x 2 row-halves; 16 strided
//   float4 loads/lane over L2-resident ctx (8 MB).
// ---------------------------------------------------------------------------
__global__ __launch_bounds__(256) void kB_combine(float* __restrict__ out) {
    __shared__ float s_e[NBLK];          // 4 KB
    __shared__ float s_red[8];
    __shared__ float s_M, s_invZ;
    __shared__ float4 s_out[8];
    int t    = threadIdx.x;
    int warp = t >> 5;
    int lane = t & 31;

    float m = fmaxf(g_m[t], fmaxf(g_m[t + 256], fmaxf(g_m[t + 512], g_m[t + 768])));
    #pragma unroll
    for (int o = 16; o > 0; o >>= 1) m = fmaxf(m, __shfl_xor_sync(0xffffffffu, m, o));
    if (lane == 0) s_red[warp] = m;
    __syncthreads();
    if (t == 0) {
        float mm = s_red[0];
        #pragma unroll
        for (int wdx = 1; wdx < 8; ++wdx) mm = fmaxf(mm, s_red[wdx]);
        s_M = mm;
    }
    __syncthreads();
    float M = s_M;

    float zs = 0.0f;
    #pragma unroll
    for (int i = 0; i < NBLK / 256; ++i) {
        int b = t + 256 * i;
        float e = __expf(g_m[b] - M);
        s_e[b] = e;
        zs += e * g_z[b];
    }
    #pragma unroll
    for (int o = 16; o > 0; o >>= 1) zs += __shfl_xor_sync(0xffffffffu, zs, o);
    __syncthreads();
    if (lane == 0) s_red[warp] = zs;
    __syncthreads();
    if (t == 0) {
        float s = 0.0f;
        #pragma unroll
        for (int wdx = 0; wdx < 8; ++wdx) s += s_red[wdx];
        s_invZ = 1.0f / s;
    }
    __syncthreads();

    int col4 = blockIdx.x * 4 + (warp >> 1);     // [0, 512)
    int half = warp & 1;
    const float4* ctx = reinterpret_cast<const float4*>(g_ctx);
    float4 acc = make_float4(0.f, 0.f, 0.f, 0.f);
    int b0 = half * (NBLK / 2) + lane;
    #pragma unroll 8
    for (int b = b0; b < half * (NBLK / 2) + NBLK / 2; b += 32) {
        float e  = s_e[b];
        float4 c = ctx[(size_t)b * (ENC_H / 4) + col4];
        acc.x += e * c.x; acc.y += e * c.y; acc.z += e * c.z; acc.w += e * c.w;
    }
    #pragma unroll
    for (int o = 16; o > 0; o >>= 1) {
        acc.x += __shfl_xor_sync(0xffffffffu, acc.x, o);
        acc.y += __shfl_xor_sync(0xffffffffu, acc.y, o);
        acc.z += __shfl_xor_sync(0xffffffffu, acc.z, o);
        acc.w += __shfl_xor_sync(0xffffffffu, acc.w, o);
    }
    if (lane == 0) s_out[warp] = acc;
    __syncthreads();
    if (t < 4) {
        float4 a = s_out[2 * t], b = s_out[2 * t + 1];
        float inv = s_invZ;
        float4 r;
        r.x = (a.x + b.x) * inv;
        r.y = (a.y + b.y) * inv;
        r.z = (a.z + b.z) * inv;
        r.w = (a.w + b.w) * inv;
        reinterpret_cast<float4*>(out)[blockIdx.x * 4 + t] = r;
    }
}

extern "C" void kernel_launch(void* const* d_in, const int* in_sizes, int n_in,
                              void* d_out, int out_size) {
    const float* enc = (const float*)d_in[0];   // [16384, 2048]
    const float* dec = (const float*)d_in[1];   // [1, 2048]
    const float* W   = (const float*)d_in[2];   // [2048, 2048]
    float* out = (float*)d_out;                 // [1, 2048]

    k1_gemv<<<N1BLK, 256>>>(W, dec);
    kA_fused<<<NBLK, 256>>>(enc);
    kB_combine<<<128, 256>>>(out);
}